// round 8
// baseline (speedup 1.0000x reference)
#include <cuda_runtime.h>
#include <math.h>

#define Bx   2
#define Mx   1024
#define Vx   300
#define Cx   128
#define HIDx 128
#define BINx 256
#define Hx   384
#define Wx   512
#define Sx   4          // seeds per block

__device__ float g_a[Vx * HIDx];          // row-major (view-major) for res gather
__device__ float g_aT[HIDx * Vx];         // transposed (neuron-major) for logits
__device__ float g_bias[Vx];

// ---------------------------------------------------------------------------
// Kernel 1: per-view anchor MLP (writes both layouts)
// ---------------------------------------------------------------------------
__global__ void view_mlp_kernel(
    const float* __restrict__ vd,
    const float* __restrict__ Wa1, const float* __restrict__ ba1,
    const float* __restrict__ Wa2, const float* __restrict__ ba2,
    const float* __restrict__ Wb1, const float* __restrict__ bb1,
    const float* __restrict__ Wb2, const float* __restrict__ bb2)
{
    const int v = blockIdx.x;
    const int t = threadIdx.x;
    __shared__ float h1[HIDx];
    __shared__ float hb[64];

    float d0 = vd[v * 3 + 0], d1 = vd[v * 3 + 1], d2 = vd[v * 3 + 2];

    float s = ba1[t];
    s = fmaf(d0, Wa1[0 * HIDx + t], s);
    s = fmaf(d1, Wa1[1 * HIDx + t], s);
    s = fmaf(d2, Wa1[2 * HIDx + t], s);
    h1[t] = fmaxf(s, 0.0f);

    if (t < 64) {
        float sb = bb1[t];
        sb = fmaf(d0, Wb1[0 * 64 + t], sb);
        sb = fmaf(d1, Wb1[1 * 64 + t], sb);
        sb = fmaf(d2, Wb1[2 * 64 + t], sb);
        hb[t] = fmaxf(sb, 0.0f);
    }
    __syncthreads();

    float acc = ba2[t];
#pragma unroll 8
    for (int i = 0; i < HIDx; i++) acc = fmaf(h1[i], Wa2[i * HIDx + t], acc);
    g_a[v * HIDx + t] = acc;
    g_aT[(size_t)t * Vx + v] = acc;

    if (t == 0) {
        float bsum = bb2[0];
        for (int k = 0; k < 64; k++) bsum = fmaf(hb[k], Wb2[k], bsum);
        g_bias[v] = bsum;
    }
}

// ---------------------------------------------------------------------------
// Kernel 2: 4 seeds per block, 256 threads (K-split halves for MLP layers).
// ---------------------------------------------------------------------------
__global__ void __launch_bounds__(256, 3) seed_kernel(
    const float* __restrict__ seed_features,   // (B,C,M)
    const int*   __restrict__ token_sel_idx,   // (B,M)
    const float* __restrict__ Kmat,            // (B,3,3)
    const float* __restrict__ depth_map,       // (B,1,H,W)
    const float* __restrict__ depth_prob,      // (B,BIN,H,W)
    const float* __restrict__ vd,              // (V,3)
    const float* __restrict__ Wq1, const float* __restrict__ bq1,
    const float* __restrict__ Wq2, const float* __restrict__ bq2,
    const float* __restrict__ Wr1, const float* __restrict__ br1,
    const float* __restrict__ Wr2, const float* __restrict__ br2,
    float* __restrict__ o_score,   // (B,M,V)
    float* __restrict__ o_top,     // (B,M)
    float* __restrict__ o_xyz,     // (B,M,3)
    float* __restrict__ o_rot,     // (B,M,3,3)
    float* __restrict__ o_res)     // (B,C,M)
{
    const int bm0 = blockIdx.x * Sx;
    const int b   = bm0 / Mx;
    const int m0  = bm0 % Mx;
    const int t   = threadIdx.x;
    const int tt  = t & 127;     // output neuron
    const int half = t >> 7;     // K half
    const int HW  = Hx * Wx;

    __shared__ __align__(16) float qin[Sx][136];
    __shared__ __align__(16) float h1[Sx][HIDx];
    __shared__ __align__(16) float part[Sx][HIDx];
    __shared__ __align__(16) float4 qsh2[HIDx];   // [neuron] -> 4 seeds
    __shared__ float wbest[Sx][8];
    __shared__ int   wbesti[Sx][8];
    __shared__ float wred[8];
    __shared__ float unc[Sx];
    __shared__ int   stop[Sx];

    // ---- entropy: 64 threads per seed, 4 bins each ----
    {
        const int se = t >> 6;           // seed 0..3
        const int le = t & 63;
        const int idx_e = token_sel_idx[b * Mx + m0 + se];
        const float* dp = depth_prob + (size_t)b * BINx * HW + idx_e;
        float ps = 0.0f;
#pragma unroll
        for (int j = 0; j < 4; j++) {
            float p = fmaxf(dp[(size_t)(le + j * 64) * HW], 1e-8f);
            ps += p * __logf(p);
        }
#pragma unroll
        for (int off = 16; off; off >>= 1) ps += __shfl_down_sync(0xffffffffu, ps, off);
        if ((t & 31) == 0) wred[t >> 5] = ps;
    }
    __syncthreads();
    if (t < Sx) {
        float u = -(wred[2 * t] + wred[2 * t + 1]) * (1.0f / 5.545177444479562f);
        unc[t] = fminf(fmaxf(u, 0.0f), 1.0f);
    }

    // ---- seed features into qin ----
    {
        const int sf = t & 3;
        const int cb = t >> 2;               // 0..63
        const float* sp = seed_features + (size_t)b * Cx * Mx + m0 + sf;
        qin[sf][cb]      = sp[(size_t)cb * Mx];
        qin[sf][cb + 64] = sp[(size_t)(cb + 64) * Mx];
    }
    __syncthreads();

    // ---- geometry: thread s handles seed s ----
    if (t < Sx) {
        const int idx = token_sel_idx[b * Mx + m0 + t];
        const float fx = Kmat[b * 9 + 0], cx = Kmat[b * 9 + 2];
        const float fy = Kmat[b * 9 + 4], cy = Kmat[b * 9 + 5];
        const int uu  = idx % Wx;
        const int vv0 = idx / Wx;

        const int hc = min(max(vv0, 1), Hx - 2);
        const int wc = min(max(uu, 1), Wx - 2);
        const float* dm = depth_map + (size_t)b * HW;
        const float zL = dm[hc * Wx + wc - 1];
        const float zR = dm[hc * Wx + wc + 1];
        const float zU = dm[(hc - 1) * Wx + wc];
        const float zD = dm[(hc + 1) * Wx + wc];

        const float xL = ((float)(wc - 1) - cx) / fx;
        const float xR = ((float)(wc + 1) - cx) / fx;
        const float xC = ((float)wc       - cx) / fx;
        const float yC = ((float)hc       - cy) / fy;
        const float yU = ((float)(hc - 1) - cy) / fy;
        const float yD = ((float)(hc + 1) - cy) / fy;

        const float dxx = xR * zR - xL * zL;
        const float dxy = yC * zR - yC * zL;
        const float dxz = zR - zL;
        const float dyx = xC * zD - xC * zU;
        const float dyy = yD * zD - yU * zU;
        const float dyz = zD - zU;

        float nx = dxy * dyz - dxz * dyy;
        float ny = dxz * dyx - dxx * dyz;
        float nz = dxx * dyy - dxy * dyx;
        const float nn = fmaxf(sqrtf(nx * nx + ny * ny + nz * nz), 1e-6f);
        nx /= nn; ny /= nn; nz /= nn;

        const float rx = ((float)uu - cx) / fx;
        const float ry = ((float)vv0 - cy) / fy;
        const float rn = fmaxf(sqrtf(rx * rx + ry * ry + 1.0f), 1e-12f);

        const float u1 = unc[t];
        const float w1 = 1.0f - u1;
        qin[t][128] = rx / rn;
        qin[t][129] = ry / rn;
        qin[t][130] = 1.0f / rn;
        qin[t][131] = nx * w1;
        qin[t][132] = ny * w1;
        qin[t][133] = nz * w1;
        qin[t][134] = u1;
    }
    __syncthreads();

    float acc[Sx];

    // ================= q layer 1 (135 -> 128), K-split 0..67 / 68..134 =====
    {
#pragma unroll
        for (int s = 0; s < Sx; s++) acc[s] = 0.0f;
        const int i0 = half ? 68 : 0;
        const int i1 = half ? 132 : 68;
        for (int i = i0; i < i1; i += 4) {
            const float w0 = Wq1[(i + 0) * HIDx + tt];
            const float w1w = Wq1[(i + 1) * HIDx + tt];
            const float w2 = Wq1[(i + 2) * HIDx + tt];
            const float w3 = Wq1[(i + 3) * HIDx + tt];
#pragma unroll
            for (int s = 0; s < Sx; s++) {
                const float4 x = *(const float4*)&qin[s][i];
                acc[s] = fmaf(x.x, w0, acc[s]);
                acc[s] = fmaf(x.y, w1w, acc[s]);
                acc[s] = fmaf(x.z, w2, acc[s]);
                acc[s] = fmaf(x.w, w3, acc[s]);
            }
        }
        if (half) {
#pragma unroll
            for (int i = 132; i < 135; i++) {
                const float w = Wq1[i * HIDx + tt];
#pragma unroll
                for (int s = 0; s < Sx; s++) acc[s] = fmaf(qin[s][i], w, acc[s]);
            }
#pragma unroll
            for (int s = 0; s < Sx; s++) part[s][tt] = acc[s];
        }
        __syncthreads();
        if (!half) {
            const float bv = bq1[tt];
#pragma unroll
            for (int s = 0; s < Sx; s++)
                h1[s][tt] = fmaxf(acc[s] + part[s][tt] + bv, 0.0f);
        }
        __syncthreads();
    }

    // ================= q layer 2 (128 -> 128) ==============================
    {
#pragma unroll
        for (int s = 0; s < Sx; s++) acc[s] = 0.0f;
        const int i0 = half * 64;
        for (int i = i0; i < i0 + 64; i += 4) {
            const float w0 = Wq2[(i + 0) * HIDx + tt];
            const float w1w = Wq2[(i + 1) * HIDx + tt];
            const float w2 = Wq2[(i + 2) * HIDx + tt];
            const float w3 = Wq2[(i + 3) * HIDx + tt];
#pragma unroll
            for (int s = 0; s < Sx; s++) {
                const float4 x = *(const float4*)&h1[s][i];
                acc[s] = fmaf(x.x, w0, acc[s]);
                acc[s] = fmaf(x.y, w1w, acc[s]);
                acc[s] = fmaf(x.z, w2, acc[s]);
                acc[s] = fmaf(x.w, w3, acc[s]);
            }
        }
        if (half) {
#pragma unroll
            for (int s = 0; s < Sx; s++) part[s][tt] = acc[s];
        }
        __syncthreads();
        if (!half) {
            const float bv = bq2[tt];
            float4 qv;
            qv.x = fmaxf(acc[0] + part[0][tt] + bv, 0.0f);
            qv.y = fmaxf(acc[1] + part[1][tt] + bv, 0.0f);
            qv.z = fmaxf(acc[2] + part[2][tt] + bv, 0.0f);
            qv.w = fmaxf(acc[3] + part[3][tt] + bv, 0.0f);
            qsh2[tt] = qv;
        }
        __syncthreads();
    }

    // ================= logits vs 300 views (thread-per-view, coalesced) ====
    {
        const float scale = 0.0883883476483184f; // 1/sqrt(128)
        float best[Sx];
        int   besti[Sx];
#pragma unroll
        for (int s = 0; s < Sx; s++) { best[s] = -1e30f; besti[s] = 0; }

        for (int v = t; v < Vx; v += 256) {
            const float* ga = g_aT + v;
            float d0 = 0.0f, d1 = 0.0f, d2 = 0.0f, d3 = 0.0f;
#pragma unroll 8
            for (int h = 0; h < HIDx; h++) {
                const float a = ga[(size_t)h * Vx];
                const float4 q = qsh2[h];
                d0 = fmaf(a, q.x, d0);
                d1 = fmaf(a, q.y, d1);
                d2 = fmaf(a, q.z, d2);
                d3 = fmaf(a, q.w, d3);
            }
            const float bvv = g_bias[v];
            float lg[Sx];
            lg[0] = fmaf(d0, scale, bvv);
            lg[1] = fmaf(d1, scale, bvv);
            lg[2] = fmaf(d2, scale, bvv);
            lg[3] = fmaf(d3, scale, bvv);
#pragma unroll
            for (int s = 0; s < Sx; s++) {
                o_score[(size_t)(bm0 + s) * Vx + v] = 1.0f / (1.0f + __expf(-lg[s]));
                if (lg[s] > best[s]) { best[s] = lg[s]; besti[s] = v; }
            }
        }

        // warp argmax reduce
        const int wid = t >> 5, lane = t & 31;
#pragma unroll
        for (int s = 0; s < Sx; s++) {
            float bv = best[s]; int bi = besti[s];
#pragma unroll
            for (int off = 16; off; off >>= 1) {
                const float ov = __shfl_down_sync(0xffffffffu, bv, off);
                const int   oi = __shfl_down_sync(0xffffffffu, bi, off);
                if (ov > bv || (ov == bv && oi < bi)) { bv = ov; bi = oi; }
            }
            if (lane == 0) { wbest[s][wid] = bv; wbesti[s][wid] = bi; }
        }
    }
    __syncthreads();

    // ---- cross-warp argmax: threads 0..31, 8 per seed ----
    if (t < 32) {
        const int s = t >> 3, l = t & 7;
        float bv = wbest[s][l]; int bi = wbesti[s][l];
#pragma unroll
        for (int off = 4; off; off >>= 1) {
            const float ov = __shfl_down_sync(0xffffffffu, bv, off, 8);
            const int   oi = __shfl_down_sync(0xffffffffu, bi, off, 8);
            if (ov > bv || (ov == bv && oi < bi)) { bv = ov; bi = oi; }
        }
        if (l == 0) stop[s] = bi;
    }
    __syncthreads();

    // ---- per-seed scalar outputs ----
    if (t < Sx) {
        const int top = stop[t];
        const int bm = bm0 + t;
        o_top[bm] = (float)top;
        const float tvx = vd[top * 3 + 0];
        const float tvy = vd[top * 3 + 1];
        const float tvz = vd[top * 3 + 2];
        o_xyz[bm * 3 + 0] = tvx;
        o_xyz[bm * 3 + 1] = tvy;
        o_xyz[bm * 3 + 2] = tvz;

        float axx = -tvx, axy = -tvy, axz = -tvz;
        float ayx = tvy,  ayy = -tvx, ayz = 0.0f;
        const float nyl = sqrtf(ayx * ayx + ayy * ayy);
        if (nyl < 1e-8f) { ayx = 0.0f; ayy = 1.0f; ayz = 0.0f; }
        else { const float inv = 1.0f / fmaxf(nyl, 1e-8f); ayx *= inv; ayy *= inv; }
        const float axn = fmaxf(sqrtf(axx * axx + axy * axy + axz * axz), 1e-8f);
        axx /= axn; axy /= axn; axz /= axn;
        const float azx = axy * ayz - axz * ayy;
        const float azy = axz * ayx - axx * ayz;
        const float azz = axx * ayy - axy * ayx;
        float* rr = o_rot + (size_t)bm * 9;
        rr[0] = axx; rr[1] = ayx; rr[2] = azx;
        rr[3] = axy; rr[4] = ayy; rr[5] = azy;
        rr[6] = axz; rr[7] = ayz; rr[8] = azz;
    }

    // ---- res input: q + a_top -> h1 (written by half0) ----
    if (!half) {
        const float4 qv = qsh2[tt];
        h1[0][tt] = qv.x + g_a[stop[0] * HIDx + tt];
        h1[1][tt] = qv.y + g_a[stop[1] * HIDx + tt];
        h1[2][tt] = qv.z + g_a[stop[2] * HIDx + tt];
        h1[3][tt] = qv.w + g_a[stop[3] * HIDx + tt];
    }
    __syncthreads();

    // ================= res layer 1 (128 -> 128) -> qin (reused) ============
    {
#pragma unroll
        for (int s = 0; s < Sx; s++) acc[s] = 0.0f;
        const int i0 = half * 64;
        for (int i = i0; i < i0 + 64; i += 4) {
            const float w0 = Wr1[(i + 0) * HIDx + tt];
            const float w1w = Wr1[(i + 1) * HIDx + tt];
            const float w2 = Wr1[(i + 2) * HIDx + tt];
            const float w3 = Wr1[(i + 3) * HIDx + tt];
#pragma unroll
            for (int s = 0; s < Sx; s++) {
                const float4 x = *(const float4*)&h1[s][i];
                acc[s] = fmaf(x.x, w0, acc[s]);
                acc[s] = fmaf(x.y, w1w, acc[s]);
                acc[s] = fmaf(x.z, w2, acc[s]);
                acc[s] = fmaf(x.w, w3, acc[s]);
            }
        }
        if (half) {
#pragma unroll
            for (int s = 0; s < Sx; s++) part[s][tt] = acc[s];
        }
        __syncthreads();
        if (!half) {
            const float bv = br1[tt];
#pragma unroll
            for (int s = 0; s < Sx; s++)
                qin[s][tt] = fmaxf(acc[s] + part[s][tt] + bv, 0.0f);
        }
        __syncthreads();
    }

    // ================= res layer 2 (128 -> 128) -> output ==================
    {
#pragma unroll
        for (int s = 0; s < Sx; s++) acc[s] = 0.0f;
        const int i0 = half * 64;
        for (int i = i0; i < i0 + 64; i += 4) {
            const float w0 = Wr2[(i + 0) * HIDx + tt];
            const float w1w = Wr2[(i + 1) * HIDx + tt];
            const float w2 = Wr2[(i + 2) * HIDx + tt];
            const float w3 = Wr2[(i + 3) * HIDx + tt];
#pragma unroll
            for (int s = 0; s < Sx; s++) {
                const float4 x = *(const float4*)&qin[s][i];
                acc[s] = fmaf(x.x, w0, acc[s]);
                acc[s] = fmaf(x.y, w1w, acc[s]);
                acc[s] = fmaf(x.z, w2, acc[s]);
                acc[s] = fmaf(x.w, w3, acc[s]);
            }
        }
        if (half) {
#pragma unroll
            for (int s = 0; s < Sx; s++) part[s][tt] = acc[s];
        }
        __syncthreads();
        if (!half) {
            const float bv = br2[tt];
            float* op = o_res + (size_t)b * Cx * Mx + (size_t)tt * Mx + m0;
#pragma unroll
            for (int s = 0; s < Sx; s++)
                op[s] = acc[s] + part[s][tt] + bv;
        }
    }
}

// ---------------------------------------------------------------------------
extern "C" void kernel_launch(void* const* d_in, const int* in_sizes, int n_in,
                              void* d_out, int out_size)
{
    const float* seed  = (const float*)d_in[0];
    const int*   tok   = (const int*)  d_in[1];
    const float* K     = (const float*)d_in[2];
    const float* dmap  = (const float*)d_in[3];
    const float* dprob = (const float*)d_in[4];
    const float* vd    = (const float*)d_in[5];
    const float* Wq1 = (const float*)d_in[6],  *bq1 = (const float*)d_in[7];
    const float* Wq2 = (const float*)d_in[8],  *bq2 = (const float*)d_in[9];
    const float* Wa1 = (const float*)d_in[10], *ba1 = (const float*)d_in[11];
    const float* Wa2 = (const float*)d_in[12], *ba2 = (const float*)d_in[13];
    const float* Wb1 = (const float*)d_in[14], *bb1 = (const float*)d_in[15];
    const float* Wb2 = (const float*)d_in[16], *bb2 = (const float*)d_in[17];
    const float* Wr1 = (const float*)d_in[18], *br1 = (const float*)d_in[19];
    const float* Wr2 = (const float*)d_in[20], *br2 = (const float*)d_in[21];

    float* out     = (float*)d_out;
    float* o_score = out;
    float* o_top   = o_score + (size_t)Bx * Mx * Vx;
    float* o_xyz   = o_top   + (size_t)Bx * Mx;
    float* o_rot   = o_xyz   + (size_t)Bx * Mx * 3;
    float* o_res   = o_rot   + (size_t)Bx * Mx * 9;

    view_mlp_kernel<<<Vx, 128>>>(vd, Wa1, ba1, Wa2, ba2, Wb1, bb1, Wb2, bb2);
    seed_kernel<<<(Bx * Mx) / Sx, 256>>>(seed, tok, K, dmap, dprob, vd,
                                         Wq1, bq1, Wq2, bq2, Wr1, br1, Wr2, br2,
                                         o_score, o_top, o_xyz, o_rot, o_res);
}

// round 10
// speedup vs baseline: 1.3047x; 1.3047x over previous
#include <cuda_runtime.h>
#include <math.h>

#define Bx   2
#define Mx   1024
#define Vx   300
#define Cx   128
#define HIDx 128
#define BINx 256
#define Hx   384
#define Wx   512
#define Sx   8          // seeds per block

__device__ float g_a[Vx * HIDx];      // view-major (res gather)
__device__ float g_aT[HIDx * Vx];     // neuron-major (logits, coalesced)
__device__ float g_bias[Vx];

// ---------------------------------------------------------------------------
// Kernel 1: per-view anchor MLP
// ---------------------------------------------------------------------------
__global__ void view_mlp_kernel(
    const float* __restrict__ vd,
    const float* __restrict__ Wa1, const float* __restrict__ ba1,
    const float* __restrict__ Wa2, const float* __restrict__ ba2,
    const float* __restrict__ Wb1, const float* __restrict__ bb1,
    const float* __restrict__ Wb2, const float* __restrict__ bb2)
{
    const int v = blockIdx.x;
    const int t = threadIdx.x;
    __shared__ float h1[HIDx];
    __shared__ float hb[64];

    float d0 = vd[v * 3 + 0], d1 = vd[v * 3 + 1], d2 = vd[v * 3 + 2];

    float s = ba1[t];
    s = fmaf(d0, Wa1[0 * HIDx + t], s);
    s = fmaf(d1, Wa1[1 * HIDx + t], s);
    s = fmaf(d2, Wa1[2 * HIDx + t], s);
    h1[t] = fmaxf(s, 0.0f);

    if (t < 64) {
        float sb = bb1[t];
        sb = fmaf(d0, Wb1[0 * 64 + t], sb);
        sb = fmaf(d1, Wb1[1 * 64 + t], sb);
        sb = fmaf(d2, Wb1[2 * 64 + t], sb);
        hb[t] = fmaxf(sb, 0.0f);
    }
    __syncthreads();

    float acc = ba2[t];
#pragma unroll 8
    for (int i = 0; i < HIDx; i++) acc = fmaf(h1[i], Wa2[i * HIDx + t], acc);
    g_a[v * HIDx + t] = acc;
    g_aT[(size_t)t * Vx + v] = acc;

    if (t == 0) {
        float bsum = bb2[0];
        for (int k = 0; k < 64; k++) bsum = fmaf(hb[k], Wb2[k], bsum);
        g_bias[v] = bsum;
    }
}

// ---------------------------------------------------------------------------
// Kernel 2: 8 seeds per block, 256 threads (K-split halves for MLP layers).
// ---------------------------------------------------------------------------
__global__ void __launch_bounds__(256) seed_kernel(
    const float* __restrict__ seed_features,   // (B,C,M)
    const int*   __restrict__ token_sel_idx,   // (B,M)
    const float* __restrict__ Kmat,            // (B,3,3)
    const float* __restrict__ depth_map,       // (B,1,H,W)
    const float* __restrict__ depth_prob,      // (B,BIN,H,W)
    const float* __restrict__ vd,              // (V,3)
    const float* __restrict__ Wq1, const float* __restrict__ bq1,
    const float* __restrict__ Wq2, const float* __restrict__ bq2,
    const float* __restrict__ Wr1, const float* __restrict__ br1,
    const float* __restrict__ Wr2, const float* __restrict__ br2,
    float* __restrict__ o_score,   // (B,M,V)
    float* __restrict__ o_top,     // (B,M)
    float* __restrict__ o_xyz,     // (B,M,3)
    float* __restrict__ o_rot,     // (B,M,3,3)
    float* __restrict__ o_res)     // (B,C,M)
{
    const int bm0 = blockIdx.x * Sx;
    const int b   = bm0 / Mx;
    const int m0  = bm0 % Mx;
    const int t   = threadIdx.x;
    const int tt  = t & 127;     // output neuron
    const int half = t >> 7;     // K half
    const int HW  = Hx * Wx;

    __shared__ __align__(16) float qin[Sx][136];
    __shared__ __align__(16) float h1[Sx][HIDx];
    __shared__ __align__(16) float part[Sx][HIDx];
    __shared__ __align__(16) float4 qTa[HIDx];   // [neuron] -> seeds 0..3
    __shared__ __align__(16) float4 qTb[HIDx];   // [neuron] -> seeds 4..7
    __shared__ float wbest[Sx][8];
    __shared__ int   wbesti[Sx][8];
    __shared__ float unc[Sx];
    __shared__ int   stop[Sx];

    // ---- entropy: 32 threads per seed, 8 bins each ----
    {
        const int se = t >> 5;
        const int le = t & 31;
        const int idx_e = token_sel_idx[b * Mx + m0 + se];
        const float* dp = depth_prob + (size_t)b * BINx * HW + idx_e;
        float ps = 0.0f;
#pragma unroll
        for (int j = 0; j < 8; j++) {
            float p = fmaxf(dp[(size_t)(le + j * 32) * HW], 1e-8f);
            ps += p * __logf(p);
        }
#pragma unroll
        for (int off = 16; off; off >>= 1) ps += __shfl_down_sync(0xffffffffu, ps, off);
        if (le == 0) {
            float u = -ps * (1.0f / 5.545177444479562f); // /ln(256)
            unc[se] = fminf(fmaxf(u, 0.0f), 1.0f);
        }
    }

    // ---- seed features into qin (coalesced) ----
    {
        const int sf = t & 7;
        const int cb = t >> 3;               // 0..31
        const float* sp = seed_features + (size_t)b * Cx * Mx + m0 + sf;
#pragma unroll
        for (int j = 0; j < 4; j++) {
            const int c = cb + 32 * j;
            qin[sf][c] = sp[(size_t)c * Mx];
        }
    }
    __syncthreads();

    // ---- geometry: thread s handles seed s ----
    if (t < Sx) {
        const int idx = token_sel_idx[b * Mx + m0 + t];
        const float fx = Kmat[b * 9 + 0], cx = Kmat[b * 9 + 2];
        const float fy = Kmat[b * 9 + 4], cy = Kmat[b * 9 + 5];
        const int uu  = idx % Wx;
        const int vv0 = idx / Wx;

        const int hc = min(max(vv0, 1), Hx - 2);
        const int wc = min(max(uu, 1), Wx - 2);
        const float* dm = depth_map + (size_t)b * HW;
        const float zL = dm[hc * Wx + wc - 1];
        const float zR = dm[hc * Wx + wc + 1];
        const float zU = dm[(hc - 1) * Wx + wc];
        const float zD = dm[(hc + 1) * Wx + wc];

        const float xL = ((float)(wc - 1) - cx) / fx;
        const float xR = ((float)(wc + 1) - cx) / fx;
        const float xC = ((float)wc       - cx) / fx;
        const float yC = ((float)hc       - cy) / fy;
        const float yU = ((float)(hc - 1) - cy) / fy;
        const float yD = ((float)(hc + 1) - cy) / fy;

        const float dxx = xR * zR - xL * zL;
        const float dxy = yC * zR - yC * zL;
        const float dxz = zR - zL;
        const float dyx = xC * zD - xC * zU;
        const float dyy = yD * zD - yU * zU;
        const float dyz = zD - zU;

        float nx = dxy * dyz - dxz * dyy;
        float ny = dxz * dyx - dxx * dyz;
        float nz = dxx * dyy - dxy * dyx;
        const float nn = fmaxf(sqrtf(nx * nx + ny * ny + nz * nz), 1e-6f);
        nx /= nn; ny /= nn; nz /= nn;

        const float rx = ((float)uu - cx) / fx;
        const float ry = ((float)vv0 - cy) / fy;
        const float rn = fmaxf(sqrtf(rx * rx + ry * ry + 1.0f), 1e-12f);

        const float u1 = unc[t];
        const float w1 = 1.0f - u1;
        qin[t][128] = rx / rn;
        qin[t][129] = ry / rn;
        qin[t][130] = 1.0f / rn;
        qin[t][131] = nx * w1;
        qin[t][132] = ny * w1;
        qin[t][133] = nz * w1;
        qin[t][134] = u1;
    }
    __syncthreads();

    float acc[Sx];

    // ================= q layer 1 (135 -> 128), K-split 0..67 / 68..134 =====
    {
#pragma unroll
        for (int s = 0; s < Sx; s++) acc[s] = 0.0f;
        const int i0 = half ? 68 : 0;
        const int i1 = half ? 132 : 68;
        for (int i = i0; i < i1; i += 4) {
            const float w0 = Wq1[(i + 0) * HIDx + tt];
            const float w1w = Wq1[(i + 1) * HIDx + tt];
            const float w2 = Wq1[(i + 2) * HIDx + tt];
            const float w3 = Wq1[(i + 3) * HIDx + tt];
#pragma unroll
            for (int s = 0; s < Sx; s++) {
                const float4 x = *(const float4*)&qin[s][i];
                acc[s] = fmaf(x.x, w0, acc[s]);
                acc[s] = fmaf(x.y, w1w, acc[s]);
                acc[s] = fmaf(x.z, w2, acc[s]);
                acc[s] = fmaf(x.w, w3, acc[s]);
            }
        }
        if (half) {
#pragma unroll
            for (int i = 132; i < 135; i++) {
                const float w = Wq1[i * HIDx + tt];
#pragma unroll
                for (int s = 0; s < Sx; s++) acc[s] = fmaf(qin[s][i], w, acc[s]);
            }
#pragma unroll
            for (int s = 0; s < Sx; s++) part[s][tt] = acc[s];
        }
        __syncthreads();
        if (!half) {
            const float bv = bq1[tt];
#pragma unroll
            for (int s = 0; s < Sx; s++)
                h1[s][tt] = fmaxf(acc[s] + part[s][tt] + bv, 0.0f);
        }
        __syncthreads();
    }

    // ================= q layer 2 (128 -> 128) ==============================
    {
#pragma unroll
        for (int s = 0; s < Sx; s++) acc[s] = 0.0f;
        const int i0 = half * 64;
        for (int i = i0; i < i0 + 64; i += 4) {
            const float w0 = Wq2[(i + 0) * HIDx + tt];
            const float w1w = Wq2[(i + 1) * HIDx + tt];
            const float w2 = Wq2[(i + 2) * HIDx + tt];
            const float w3 = Wq2[(i + 3) * HIDx + tt];
#pragma unroll
            for (int s = 0; s < Sx; s++) {
                const float4 x = *(const float4*)&h1[s][i];
                acc[s] = fmaf(x.x, w0, acc[s]);
                acc[s] = fmaf(x.y, w1w, acc[s]);
                acc[s] = fmaf(x.z, w2, acc[s]);
                acc[s] = fmaf(x.w, w3, acc[s]);
            }
        }
        if (half) {
#pragma unroll
            for (int s = 0; s < Sx; s++) part[s][tt] = acc[s];
        }
        __syncthreads();
        if (!half) {
            const float bv = bq2[tt];
            float4 qa, qb;
            qa.x = fmaxf(acc[0] + part[0][tt] + bv, 0.0f);
            qa.y = fmaxf(acc[1] + part[1][tt] + bv, 0.0f);
            qa.z = fmaxf(acc[2] + part[2][tt] + bv, 0.0f);
            qa.w = fmaxf(acc[3] + part[3][tt] + bv, 0.0f);
            qb.x = fmaxf(acc[4] + part[4][tt] + bv, 0.0f);
            qb.y = fmaxf(acc[5] + part[5][tt] + bv, 0.0f);
            qb.z = fmaxf(acc[6] + part[6][tt] + bv, 0.0f);
            qb.w = fmaxf(acc[7] + part[7][tt] + bv, 0.0f);
            qTa[tt] = qa;
            qTb[tt] = qb;
        }
        __syncthreads();
    }

    // ================= logits vs 300 views (thread-per-view, coalesced) ====
    {
        const float scale = 0.0883883476483184f; // 1/sqrt(128)
        float best[Sx];
        int   besti[Sx];
#pragma unroll
        for (int s = 0; s < Sx; s++) { best[s] = -1e30f; besti[s] = 0; }

        for (int v = t; v < Vx; v += 256) {
            const float* ga = g_aT + v;
            float lg[Sx];
#pragma unroll
            for (int s = 0; s < Sx; s++) lg[s] = 0.0f;
#pragma unroll 8
            for (int h = 0; h < HIDx; h++) {
                const float a = ga[(size_t)h * Vx];
                const float4 qa = qTa[h];
                const float4 qb = qTb[h];
                lg[0] = fmaf(a, qa.x, lg[0]);
                lg[1] = fmaf(a, qa.y, lg[1]);
                lg[2] = fmaf(a, qa.z, lg[2]);
                lg[3] = fmaf(a, qa.w, lg[3]);
                lg[4] = fmaf(a, qb.x, lg[4]);
                lg[5] = fmaf(a, qb.y, lg[5]);
                lg[6] = fmaf(a, qb.z, lg[6]);
                lg[7] = fmaf(a, qb.w, lg[7]);
            }
            const float bvv = g_bias[v];
#pragma unroll
            for (int s = 0; s < Sx; s++) {
                const float logit = fmaf(lg[s], scale, bvv);
                o_score[(size_t)(bm0 + s) * Vx + v] = 1.0f / (1.0f + __expf(-logit));
                if (logit > best[s]) { best[s] = logit; besti[s] = v; }
            }
        }

        // warp argmax reduce
        const int wid = t >> 5, lane = t & 31;
#pragma unroll
        for (int s = 0; s < Sx; s++) {
            float bv = best[s]; int bi = besti[s];
#pragma unroll
            for (int off = 16; off; off >>= 1) {
                const float ov = __shfl_down_sync(0xffffffffu, bv, off);
                const int   oi = __shfl_down_sync(0xffffffffu, bi, off);
                if (ov > bv || (ov == bv && oi < bi)) { bv = ov; bi = oi; }
            }
            if (lane == 0) { wbest[s][wid] = bv; wbesti[s][wid] = bi; }
        }
    }
    __syncthreads();

    // ---- cross-warp argmax: threads 0..63, 8 per seed ----
    if (t < 64) {
        const int s = t >> 3, l = t & 7;
        float bv = wbest[s][l]; int bi = wbesti[s][l];
#pragma unroll
        for (int off = 4; off; off >>= 1) {
            const float ov = __shfl_down_sync(0xffffffffu, bv, off, 8);
            const int   oi = __shfl_down_sync(0xffffffffu, bi, off, 8);
            if (ov > bv || (ov == bv && oi < bi)) { bv = ov; bi = oi; }
        }
        if (l == 0) stop[s] = bi;
    }
    __syncthreads();

    // ---- per-seed scalar outputs ----
    if (t < Sx) {
        const int top = stop[t];
        const int bm = bm0 + t;
        o_top[bm] = (float)top;
        const float tvx = vd[top * 3 + 0];
        const float tvy = vd[top * 3 + 1];
        const float tvz = vd[top * 3 + 2];
        o_xyz[bm * 3 + 0] = tvx;
        o_xyz[bm * 3 + 1] = tvy;
        o_xyz[bm * 3 + 2] = tvz;

        float axx = -tvx, axy = -tvy, axz = -tvz;
        float ayx = tvy,  ayy = -tvx, ayz = 0.0f;
        const float nyl = sqrtf(ayx * ayx + ayy * ayy);
        if (nyl < 1e-8f) { ayx = 0.0f; ayy = 1.0f; ayz = 0.0f; }
        else { const float inv = 1.0f / fmaxf(nyl, 1e-8f); ayx *= inv; ayy *= inv; }
        const float axn = fmaxf(sqrtf(axx * axx + axy * axy + axz * axz), 1e-8f);
        axx /= axn; axy /= axn; axz /= axn;
        const float azx = axy * ayz - axz * ayy;
        const float azy = axz * ayx - axx * ayz;
        const float azz = axx * ayy - axy * ayx;
        float* rr = o_rot + (size_t)bm * 9;
        rr[0] = axx; rr[1] = ayx; rr[2] = azx;
        rr[3] = axy; rr[4] = ayy; rr[5] = azy;
        rr[6] = axz; rr[7] = ayz; rr[8] = azz;
    }

    // ---- res input: q + a_top -> h1 (written by half0) ----
    if (!half) {
        const float4 qa = qTa[tt];
        const float4 qb = qTb[tt];
        h1[0][tt] = qa.x + g_a[stop[0] * HIDx + tt];
        h1[1][tt] = qa.y + g_a[stop[1] * HIDx + tt];
        h1[2][tt] = qa.z + g_a[stop[2] * HIDx + tt];
        h1[3][tt] = qa.w + g_a[stop[3] * HIDx + tt];
        h1[4][tt] = qb.x + g_a[stop[4] * HIDx + tt];
        h1[5][tt] = qb.y + g_a[stop[5] * HIDx + tt];
        h1[6][tt] = qb.z + g_a[stop[6] * HIDx + tt];
        h1[7][tt] = qb.w + g_a[stop[7] * HIDx + tt];
    }
    __syncthreads();

    // ================= res layer 1 (128 -> 128) -> qin (reused) ============
    {
#pragma unroll
        for (int s = 0; s < Sx; s++) acc[s] = 0.0f;
        const int i0 = half * 64;
        for (int i = i0; i < i0 + 64; i += 4) {
            const float w0 = Wr1[(i + 0) * HIDx + tt];
            const float w1w = Wr1[(i + 1) * HIDx + tt];
            const float w2 = Wr1[(i + 2) * HIDx + tt];
            const float w3 = Wr1[(i + 3) * HIDx + tt];
#pragma unroll
            for (int s = 0; s < Sx; s++) {
                const float4 x = *(const float4*)&h1[s][i];
                acc[s] = fmaf(x.x, w0, acc[s]);
                acc[s] = fmaf(x.y, w1w, acc[s]);
                acc[s] = fmaf(x.z, w2, acc[s]);
                acc[s] = fmaf(x.w, w3, acc[s]);
            }
        }
        if (half) {
#pragma unroll
            for (int s = 0; s < Sx; s++) part[s][tt] = acc[s];
        }
        __syncthreads();
        if (!half) {
            const float bv = br1[tt];
#pragma unroll
            for (int s = 0; s < Sx; s++)
                qin[s][tt] = fmaxf(acc[s] + part[s][tt] + bv, 0.0f);
        }
        __syncthreads();
    }

    // ================= res layer 2 (128 -> 128) -> output ==================
    {
#pragma unroll
        for (int s = 0; s < Sx; s++) acc[s] = 0.0f;
        const int i0 = half * 64;
        for (int i = i0; i < i0 + 64; i += 4) {
            const float w0 = Wr2[(i + 0) * HIDx + tt];
            const float w1w = Wr2[(i + 1) * HIDx + tt];
            const float w2 = Wr2[(i + 2) * HIDx + tt];
            const float w3 = Wr2[(i + 3) * HIDx + tt];
#pragma unroll
            for (int s = 0; s < Sx; s++) {
                const float4 x = *(const float4*)&qin[s][i];
                acc[s] = fmaf(x.x, w0, acc[s]);
                acc[s] = fmaf(x.y, w1w, acc[s]);
                acc[s] = fmaf(x.z, w2, acc[s]);
                acc[s] = fmaf(x.w, w3, acc[s]);
            }
        }
        if (half) {
#pragma unroll
            for (int s = 0; s < Sx; s++) part[s][tt] = acc[s];
        }
        __syncthreads();
        if (!half) {
            const float bv = br2[tt];
            float* op = o_res + (size_t)b * Cx * Mx + (size_t)tt * Mx + m0;
#pragma unroll
            for (int s = 0; s < Sx; s++)
                op[s] = acc[s] + part[s][tt] + bv;
        }
    }
}

// ---------------------------------------------------------------------------
extern "C" void kernel_launch(void* const* d_in, const int* in_sizes, int n_in,
                              void* d_out, int out_size)
{
    const float* seed  = (const float*)d_in[0];
    const int*   tok   = (const int*)  d_in[1];
    const float* K     = (const float*)d_in[2];
    const float* dmap  = (const float*)d_in[3];
    const float* dprob = (const float*)d_in[4];
    const float* vd    = (const float*)d_in[5];
    const float* Wq1 = (const float*)d_in[6],  *bq1 = (const float*)d_in[7];
    const float* Wq2 = (const float*)d_in[8],  *bq2 = (const float*)d_in[9];
    const float* Wa1 = (const float*)d_in[10], *ba1 = (const float*)d_in[11];
    const float* Wa2 = (const float*)d_in[12], *ba2 = (const float*)d_in[13];
    const float* Wb1 = (const float*)d_in[14], *bb1 = (const float*)d_in[15];
    const float* Wb2 = (const float*)d_in[16], *bb2 = (const float*)d_in[17];
    const float* Wr1 = (const float*)d_in[18], *br1 = (const float*)d_in[19];
    const float* Wr2 = (const float*)d_in[20], *br2 = (const float*)d_in[21];

    float* out     = (float*)d_out;
    float* o_score = out;
    float* o_top   = o_score + (size_t)Bx * Mx * Vx;
    float* o_xyz   = o_top   + (size_t)Bx * Mx;
    float* o_rot   = o_xyz   + (size_t)Bx * Mx * 3;
    float* o_res   = o_rot   + (size_t)Bx * Mx * 9;

    view_mlp_kernel<<<Vx, 128>>>(vd, Wa1, ba1, Wa2, ba2, Wb1, bb1, Wb2, bb2);
    seed_kernel<<<(Bx * Mx) / Sx, 256>>>(seed, tok, K, dmap, dprob, vd,
                                         Wq1, bq1, Wq2, bq2, Wr1, br1, Wr2, br2,
                                         o_score, o_top, o_xyz, o_rot, o_res);
}